// round 13
// baseline (speedup 1.0000x reference)
#include <cuda_runtime.h>
#include <cstdint>

// Block-diagonal grouped conv2d: 64 groups, 4 in-ch -> 4 out-ch per group, 3x3, pad 1.
// x:   (32, 256, 128, 128) fp32, channel index = ci*64 + head
// w:   (64, 4, 4, 3, 3)          w[head][co][ci][ky][kx]
// b:   (64, 4)
// out: (32, 256, 128, 128) fp32, channel index = co*64 + head
//
// v13: register-diet build for 10 CTAs/SM (40 warps). 128 threads, TY=8,
//      warp = rows {wrp, wrp+4} processed sequentially (acc halved to 8 u64),
//      cp.async staging, row-major smem, co-pair f32x2 FMA core.

#define TY 8
#define SROWS (TY + 2)               // 10
#define SROW_P 132                   // row stride (floats); only 128 used
#define PLANE_P (SROWS * SROW_P)     // 1320
#define S_IN_FLOATS (4 * PLANE_P)    // 5280
#define THREADS 128
#define H 128
#define W 128
#define PLANE (H * W)
// s_in + 72 weight u64 + 2 bias u64
#define SMEM_BYTES (S_IN_FLOATS * 4 + 74 * 8)

typedef unsigned long long u64;

__device__ __forceinline__ u64 pk(float lo, float hi) {
    u64 r; asm("mov.b64 %0, {%1, %2};" : "=l"(r) : "f"(lo), "f"(hi)); return r;
}
__device__ __forceinline__ void upk(u64 v, float &lo, float &hi) {
    asm("mov.b64 {%0, %1}, %2;" : "=f"(lo), "=f"(hi) : "l"(v));
}
// d += a*b  (packed 2x fp32)
__device__ __forceinline__ void ffma2(u64 &d, u64 a, u64 b) {
    asm("fma.rn.f32x2 %0, %1, %2, %0;" : "+l"(d) : "l"(a), "l"(b));
}
__device__ __forceinline__ void cpasync16(uint32_t saddr, const float* g, bool pred) {
    int sz = pred ? 16 : 0;
    asm volatile("cp.async.cg.shared.global [%0], [%1], 16, %2;\n"
                 :: "r"(saddr), "l"(g), "r"(sz));
}

__global__ __launch_bounds__(THREADS, 10)
void bdconv_kernel(const float* __restrict__ x, const float* __restrict__ w,
                   const float* __restrict__ bias, float* __restrict__ out) {
    extern __shared__ __align__(16) float smem[];
    float* s_in = smem;                          // [ci][r][col], row-major
    u64*   s_w  = (u64*)(smem + S_IN_FLOATS);    // [ci][ky][kx][cp] co-pair
    u64*   s_b  = s_w + 72;                      // [cp]

    const int blk  = blockIdx.x;
    const int tile = blk & 15;          // 16 row-tiles of 8
    const int head = (blk >> 4) & 63;
    const int b    = blk >> 10;
    const int y0   = tile * TY;
    const int tid  = threadIdx.x;
    const int wrp  = tid >> 5;
    const int lane = tid & 31;

    // ---- stage input via cp.async: 4 warps x 10 (ci,row) pairs ----
    {
        const float* xb = x + ((long long)b * 256 + head) * PLANE;  // ci stride 64*PLANE
        const int xo = lane << 2;
        const uint32_t sbase =
            (uint32_t)__cvta_generic_to_shared(s_in) + (uint32_t)(xo * 4);
        #pragma unroll
        for (int k = 0; k < 10; k++) {
            const int rr = wrp + (k << 2);            // 0..39
            const int ci = rr / SROWS;
            const int r  = rr - ci * SROWS;
            const int y  = y0 - 1 + r;
            const bool ok = (y >= 0) && (y < H);
            const int yc = ok ? y : 0;
            cpasync16(sbase + (uint32_t)((ci * PLANE_P + r * SROW_P) * 4),
                      xb + ci * (64 * PLANE) + yc * W + xo, ok);
        }
        asm volatile("cp.async.commit_group;\n");
    }

    // ---- stage weights as co-pair float2 + bias pairs ----
    if (tid < 72) {
        const int cp  = tid & 1;            // co pair: (2cp, 2cp+1)
        const int t9  = (tid >> 1) % 9;     // ky*3+kx
        const int ci  = (tid >> 1) / 9;
        const float w0 = w[((head * 4 + 2 * cp)     * 4 + ci) * 9 + t9];
        const float w1 = w[((head * 4 + 2 * cp + 1) * 4 + ci) * 9 + t9];
        s_w[(ci * 9 + t9) * 2 + cp] = pk(w0, w1);
    }
    if (tid < 2)
        s_b[tid] = pk(bias[head * 4 + 2 * tid], bias[head * 4 + 2 * tid + 1]);

    asm volatile("cp.async.wait_group 0;\n");
    __syncthreads();

    // ---- compute: warp handles rows {wrp, wrp+4}, one at a time ----
    const int xo = lane << 2;
    float* outb = out + (((long long)b * 256 + head) * H + y0) * W + xo;

    #pragma unroll 1
    for (int rw = 0; rw < 2; rw++) {
        const int row = wrp + (rw << 2);          // 0..7

        u64 acc0[4], acc1[4];          // acc0=(co0,co1), acc1=(co2,co3)
        {
            const u64 b0 = s_b[0];
            const u64 b1 = s_b[1];
            #pragma unroll
            for (int q = 0; q < 4; q++) { acc0[q] = b0; acc1[q] = b1; }
        }

        const float* pl0 = s_in + row * SROW_P + xo;
        const u64*   wci = s_w;

        #pragma unroll 1
        for (int ci = 0; ci < 4; ci++) {
            #pragma unroll
            for (int ky = 0; ky < 3; ky++) {
                float4 B = *(const float4*)(pl0 + ky * SROW_P);

                float A = __shfl_up_sync(0xffffffffu, B.w, 1);
                float E = __shfl_down_sync(0xffffffffu, B.x, 1);
                if (lane == 0)  A = 0.0f;     // x = -1
                if (lane == 31) E = 0.0f;     // x = 128

                u64 dv[6];
                dv[0] = pk(A, A);
                dv[1] = pk(B.x, B.x);
                dv[2] = pk(B.y, B.y);
                dv[3] = pk(B.z, B.z);
                dv[4] = pk(B.w, B.w);
                dv[5] = pk(E, E);

                const ulonglong2* wp = (const ulonglong2*)(wci + ky * 6);
                const ulonglong2 wv0 = wp[0], wv1 = wp[1], wv2 = wp[2];

                #pragma unroll
                for (int q = 0; q < 4; q++) {
                    ffma2(acc0[q], wv0.x, dv[q]);
                    ffma2(acc1[q], wv0.y, dv[q]);
                    ffma2(acc0[q], wv1.x, dv[q + 1]);
                    ffma2(acc1[q], wv1.y, dv[q + 1]);
                    ffma2(acc0[q], wv2.x, dv[q + 2]);
                    ffma2(acc1[q], wv2.y, dv[q + 2]);
                }
            }
            pl0 += PLANE_P;
            wci += 18;
        }

        // store: 4 co, STG.128 coalesced across the warp
        float* obase = outb + (long long)row * W;
        float l0[4], h0[4], l1[4], h1[4];
        #pragma unroll
        for (int q = 0; q < 4; q++) {
            upk(acc0[q], l0[q], h0[q]);
            upk(acc1[q], l1[q], h1[q]);
        }
        *(float4*)(obase)                          = make_float4(l0[0], l0[1], l0[2], l0[3]);
        *(float4*)(obase + (long long) 64 * PLANE) = make_float4(h0[0], h0[1], h0[2], h0[3]);
        *(float4*)(obase + (long long)128 * PLANE) = make_float4(l1[0], l1[1], l1[2], l1[3]);
        *(float4*)(obase + (long long)192 * PLANE) = make_float4(h1[0], h1[1], h1[2], h1[3]);
    }
}

extern "C" void kernel_launch(void* const* d_in, const int* in_sizes, int n_in,
                              void* d_out, int out_size) {
    const float* x    = (const float*)d_in[0];
    const float* w    = (const float*)d_in[1];
    const float* bias = (const float*)d_in[2];
    float* out        = (float*)d_out;
    (void)in_sizes; (void)n_in; (void)out_size;
    cudaFuncSetAttribute(bdconv_kernel,
                         cudaFuncAttributeMaxDynamicSharedMemorySize, SMEM_BYTES);
    bdconv_kernel<<<32 * 64 * 16, THREADS, SMEM_BYTES>>>(x, w, bias, out);
}